// round 6
// baseline (speedup 1.0000x reference)
#include <cuda_runtime.h>
#include <math.h>

// SigmoidGatedCRFLoss, pairwise-collapsed, single fused kernel, dy-split for occupancy.
// loss = [ Σ_{p,q} md(p)·ms(q)·g(Δ)·(0.9·e^{-50|Δrgb|²}+0.1)·(s_p(1-s_q)+s_q(1-s_p)) ] / max(Σ md, 1)
//
// Per pixel p:  contrib = md_p · ( s_p·SB + (1-s_p)·SA ),  (linear in SA,SB → dy-splittable)
//   SA = Σ_q w(p,q)·A_q,  SB = Σ_q w(p,q)·B_q,  A=ms·s, B=ms·(1-s)
//   w = G9(Δxy)·(e_rgb + 1/9),  G9 = 0.9·exp(-(dx²+dy²)/72) (0 at center)
//   e_rgb = 2^(-Σ diff²) with rgb pre-scaled by sqrt(50·log2 e)  == exp(-50|Δrgb|²)

#define RAD   5
#define DIAM  11
#define BX    16            // threads in x
#define BY    8             // threads in y
#define TW    (BX * 2)      // 32-px-wide tile (2 px per thread)
#define TH    BY            // 8
#define HW_   (TW + 2*RAD)  // 42
#define HHMAX 13            // max halo rows for a dy-half (TH + 5)
#define HALFW ((HW_ + 1)/2) // 21
#define NT    (BX * BY)     // 128 threads

#define RGB_SCALE 8.493218f // sqrt(50 * log2(e))

__device__ double   g_num;
__device__ double   g_den;
__device__ unsigned g_ticket;

__device__ __forceinline__ float fast_ex2(float x) {
    float r;
    asm("ex2.approx.f32 %0, %1;" : "=f"(r) : "f"(x));
    return r;
}

__global__ __launch_bounds__(NT, 8) void crf_loss_kernel(
    const float* __restrict__ x,      // [N,3,H,W]
    const float* __restrict__ y,      // [N,H,W]
    const float* __restrict__ msrc,   // [N,1,H,W]
    const float* __restrict__ mdst,   // [N,1,H,W]
    float* __restrict__ out,
    int H, int W, unsigned nblocks)
{
    // even/odd column split -> unit-stride lane addressing (no bank conflicts)
    __shared__ float4 sEv[HHMAX][HALFW];   // r,g,b (scaled), A = ms*s  (even cols)
    __shared__ float4 sOd[HHMAX][HALFW];
    __shared__ float  sBEv[HHMAX][HALFW];  // B = ms*(1-s)
    __shared__ float  sBOd[HHMAX][HALFW];
    __shared__ __align__(16) float sG[DIAM * 12];  // 0.9*gauss, rows padded to 12
    __shared__ float  red[8];

    const int zz   = blockIdx.z;
    const int n    = zz >> 1;
    const int half = zz & 1;
    const int d0   = half ? 6 : 0;         // dy range [d0, d0+nDy)
    const int nDy  = half ? 5 : 6;
    const int tx0  = blockIdx.x * TW;
    const int ty0  = blockIdx.y * TH;
    const int tid  = threadIdx.y * BX + threadIdx.x;
    const int HWp  = H * W;

    const float* __restrict__ xr = x + (size_t)n * 3 * HWp;
    const float* __restrict__ xg = xr + HWp;
    const float* __restrict__ xb = xr + 2 * HWp;
    const float* __restrict__ yp = y    + (size_t)n * HWp;
    const float* __restrict__ mp = msrc + (size_t)n * HWp;
    const float* __restrict__ dp = mdst + (size_t)n * HWp;

    // Spatial gaussian table (row-padded to 12): G9 = 0.9*exp(-(dx^2+dy^2)/72),
    // center zeroed (implements kernels[:,:,center]=0 for both descriptors).
    for (int i = tid; i < DIAM * 12; i += NT) {
        int dy = i / 12, dx = i % 12;
        float g = 0.0f;
        if (dx < DIAM) {
            int ddx = dx - RAD, ddy = dy - RAD;
            g = 0.9f * __expf(-(float)(ddx*ddx + ddy*ddy) * (1.0f / 72.0f));
            if (ddx == 0 && ddy == 0) g = 0.0f;
        }
        sG[i] = g;
    }

    // Halo fill for this dy-half: rows [ty0+d0-RAD, ty0+TH-1+d0+nDy-1-RAD].
    // OOB -> zeros == unfold's zero padding of the binarized mask.
    const int hRows = TH + nDy - 1;        // 13 (half0) / 12 (half1)
    const int hsz   = HW_ * hRows;
    for (int i = tid; i < hsz; i += NT) {
        int ly = i / HW_;
        int lx = i - ly * HW_;
        int gy = ty0 + d0 - RAD + ly;
        int gx = tx0 + lx - RAD;
        float r = 0.f, g = 0.f, b = 0.f, A = 0.f, B = 0.f;
        if (gx >= 0 && gx < W && gy >= 0 && gy < H) {
            int idx = gy * W + gx;
            float ms = mp[idx];
            if (isnan(ms) || ms < 1.0f) ms = 0.0f;    // binarize, keep value if >=1
            float s = 1.0f / (1.0f + __expf(-yp[idx]));
            r = xr[idx] * RGB_SCALE;
            g = xg[idx] * RGB_SCALE;
            b = xb[idx] * RGB_SCALE;
            A = ms * s;
            B = ms - A;                               // ms*(1-s)
        }
        float4 v = make_float4(r, g, b, A);
        int h = lx >> 1;
        if (lx & 1) { sOd[ly][h] = v; sBOd[ly][h] = B; }
        else        { sEv[ly][h] = v; sBEv[ly][h] = B; }
    }
    __syncthreads();

    const int cx  = threadIdx.x;           // 0..15
    const int cy  = threadIdx.y;           // 0..7
    const int px0 = tx0 + 2 * cx;
    const int py  = ty0 + cy;

    // Center rgb from gmem (center row isn't in half1's halo); L1/L2-cached.
    float4 c0, c1;
    {
        int i0 = py * W + px0;
        c0 = make_float4(xr[i0] * RGB_SCALE, xg[i0] * RGB_SCALE, xb[i0] * RGB_SCALE, 0.f);
        c1 = make_float4(xr[i0 + 1] * RGB_SCALE, xg[i0 + 1] * RGB_SCALE, xb[i0 + 1] * RGB_SCALE, 0.f);
    }

    float SA0 = 0.f, SB0 = 0.f, SA1 = 0.f, SB1 = 0.f;

    #define TAP(q, Bq, Gv, c, SA, SB) do {                                   \
        float dr_ = (q).x - (c).x;                                           \
        float dg_ = (q).y - (c).y;                                           \
        float db_ = (q).z - (c).z;                                           \
        float d2n_ = fmaf(dr_, -dr_, fmaf(dg_, -dg_, db_ * (-db_)));         \
        float e_  = fast_ex2(d2n_);                                          \
        float w_  = (e_ + 0.11111111f) * (Gv);                               \
        SA = fmaf(w_, (q).w, SA);                                            \
        SB = fmaf(w_, (Bq), SB);                                             \
    } while (0)

    for (int dyi = 0; dyi < nDy; dyi++) {
        const int row = cy + dyi;                    // halo-local row
        const float4* __restrict__ ev  = &sEv[row][cx];
        const float4* __restrict__ od  = &sOd[row][cx];
        const float*  __restrict__ bev = &sBEv[row][cx];
        const float*  __restrict__ bod = &sBOd[row][cx];

        float gr[12];
        {
            const int gbase = (d0 + dyi) * 12;
            ((float4*)gr)[0] = *(const float4*)&sG[gbase + 0];
            ((float4*)gr)[1] = *(const float4*)&sG[gbase + 4];
            ((float4*)gr)[2] = *(const float4*)&sG[gbase + 8];
        }

        #pragma unroll
        for (int j = 0; j < 12; j++) {
            // window col (local) = 2cx + j; even j -> Ev[cx+j/2], odd -> Od[cx+(j-1)/2]
            float4 q;
            float  Bq;
            if (j & 1) { q = od[(j - 1) >> 1]; Bq = bod[(j - 1) >> 1]; }
            else       { q = ev[j >> 1];       Bq = bev[j >> 1];       }
            if (j < 11) TAP(q, Bq, gr[j],     c0, SA0, SB0);  // pixel0 dx = j
            if (j > 0)  TAP(q, Bq, gr[j - 1], c1, SA1, SB1);  // pixel1 dx = j-1
        }
    }

    // Center-pixel combine (partial over this dy-half; linear in SA/SB).
    float num = 0.f, den = 0.f;
    if (py < H) {
        if (px0 < W) {
            int idx = py * W + px0;
            float md = dp[idx];
            if (isnan(md) || md < 1.0f) md = 0.0f;
            float sp = 1.0f / (1.0f + __expf(-yp[idx]));
            num += md * fmaf(sp, SB0, (1.0f - sp) * SA0);
            if (half == 0) den += md;                 // count denominator once
        }
        if (px0 + 1 < W) {
            int idx = py * W + px0 + 1;
            float md = dp[idx];
            if (isnan(md) || md < 1.0f) md = 0.0f;
            float sp = 1.0f / (1.0f + __expf(-yp[idx]));
            num += md * fmaf(sp, SB1, (1.0f - sp) * SA1);
            if (half == 0) den += md;
        }
    }

    // Block reduction
    #pragma unroll
    for (int off = 16; off > 0; off >>= 1) {
        num += __shfl_down_sync(0xffffffffu, num, off);
        den += __shfl_down_sync(0xffffffffu, den, off);
    }
    int wid = tid >> 5, lid = tid & 31;
    if (lid == 0) { red[wid] = num; red[4 + wid] = den; }
    __syncthreads();

    if (tid == 0) {
        float ns = red[0] + red[1] + red[2] + red[3];
        float ds = red[4] + red[5] + red[6] + red[7];
        atomicAdd(&g_num, (double)ns);
        atomicAdd(&g_den, (double)ds);
        __threadfence();
        unsigned old = atomicAdd(&g_ticket, 1u);
        if (old == nblocks - 1u) {            // last block finalizes + resets
            double nn = g_num;
            double dd = g_den;
            if (dd < 1.0) dd = 1.0;
            out[0] = (float)(nn / dd);
            g_num = 0.0;
            g_den = 0.0;
            g_ticket = 0u;
        }
    }
}

extern "C" void kernel_launch(void* const* d_in, const int* in_sizes, int n_in,
                              void* d_out, int out_size) {
    const float* x    = (const float*)d_in[0];
    const float* y    = (const float*)d_in[1];
    const float* msrc = (const float*)d_in[2];
    const float* mdst = (const float*)d_in[3];
    float* out = (float*)d_out;

    const int H = 256, W = 256;
    const int N = in_sizes[1] / (H * W);

    dim3 block(BX, BY, 1);
    dim3 grid((W + TW - 1) / TW, (H + TH - 1) / TH, 2 * N);  // dy-split: 2 blocks/tile
    unsigned nblocks = grid.x * grid.y * grid.z;
    crf_loss_kernel<<<grid, block>>>(x, y, msrc, mdst, out, H, W, nblocks);
}

// round 7
// speedup vs baseline: 1.0152x; 1.0152x over previous
#include <cuda_runtime.h>
#include <cuda_fp16.h>
#include <math.h>

// SigmoidGatedCRFLoss — pairwise-collapsed, fp16/half2 pipeline, dy-split.
// loss = [ Σ_{p,q} md(p)·ms(q)·G(Δ)·(0.9·e^{-50|Δrgb|²}+0.1)·(s_p(1-s_q)+s_q(1-s_p)) ] / max(Σ md,1)
// Per pixel:  num_p = md_p·(s_p·SB + (1-s_p)·SA),  SA=Σ w·A, SB=Σ w·B, A=ms·s, B=ms·(1-s)
//   w = G9·(e + 1/9),  G9 = 0.9·exp(-(dx²+dy²)/72) (0 at center)
//   e  = 2^(-Σ du²), u = rgb · sqrt(50·log2 e)  ==  exp(-50·|Δrgb|²)

#define RAD    5
#define DIAM   11
#define BX     32           // lanes: one warp spans a full smem row
#define BY     4
#define TW     (BX * 2)     // 64-px-wide tile, 2 px per thread
#define TH     BY           // 4
#define HW_    (TW + 2*RAD) // 74 halo cols
#define HROWS  9            // max halo rows per dy-half (TH + 6 - 1)
#define HC     38           // half2 per row (37 used, +1 pad)
#define NT     (BX * BY)    // 128 threads

#define RGB_SCALE 8.4932178f   // sqrt(50 * log2(e))

__device__ double   g_num;
__device__ double   g_den;
__device__ unsigned g_ticket;

__global__ __launch_bounds__(NT, 8) void crf_loss_kernel(
    const float* __restrict__ x,      // [N,3,H,W]
    const float* __restrict__ y,      // [N,H,W]
    const float* __restrict__ msrc,   // [N,1,H,W]
    const float* __restrict__ mdst,   // [N,1,H,W]
    float* __restrict__ out,
    int H, int W, unsigned nblocks)
{
    // SoA fp16 halo; each warp row-access is unit-stride -> conflict-free
    __shared__ __half2 sR [HROWS][HC];
    __shared__ __half2 sGg[HROWS][HC];
    __shared__ __half2 sBb[HROWS][HC];
    __shared__ __half2 sA [HROWS][HC];
    __shared__ __half2 sB [HROWS][HC];
    __shared__ __half2 sGp0[DIAM][6];   // pixel0 weight pairs (g[2k], g[2k+1])
    __shared__ __half2 sGp1[DIAM][6];   // pixel1 weight pairs (g[2k-1], g[2k])
    __shared__ float   red[8];

    const int zz   = blockIdx.z;
    const int n    = zz >> 1;
    const int half = zz & 1;
    const int d0   = half ? 6 : 0;       // dy range [d0, d0+nDy)
    const int nDy  = half ? 5 : 6;
    const int tx0  = blockIdx.x * TW;
    const int ty0  = blockIdx.y * TH;
    const int cx   = threadIdx.x;        // 0..31
    const int cy   = threadIdx.y;        // 0..3
    const int tid  = cy * BX + cx;
    const int HWp  = H * W;

    const float* __restrict__ xr = x + (size_t)n * 3 * HWp;
    const float* __restrict__ xg = xr + HWp;
    const float* __restrict__ xb = xr + 2 * HWp;
    const float* __restrict__ yp = y    + (size_t)n * HWp;
    const float* __restrict__ mp = msrc + (size_t)n * HWp;
    const float* __restrict__ dp = mdst + (size_t)n * HWp;

    // Spatial gaussian weight pairs; g(dx,dy)=0.9*exp(-((dx-5)^2+(dy-5)^2)/72),
    // center zeroed, out-of-range dx -> 0 (pads the shifted pixel1/pixel0 pairs).
    for (int i = tid; i < DIAM * 6; i += NT) {
        int row = i / 6, k = i % 6;
        int ddy = row - RAD;
        float gv[3];                     // dx = 2k-1, 2k, 2k+1
        #pragma unroll
        for (int t = 0; t < 3; t++) {
            int dx = 2 * k - 1 + t;
            float g = 0.0f;
            if (dx >= 0 && dx < DIAM) {
                int ddx = dx - RAD;
                g = 0.9f * __expf(-(float)(ddx * ddx + ddy * ddy) * (1.0f / 72.0f));
                if (ddx == 0 && ddy == 0) g = 0.0f;
            }
            gv[t] = g;
        }
        sGp0[row][k] = __floats2half2_rn(gv[1], gv[2]);
        sGp1[row][k] = __floats2half2_rn(gv[0], gv[1]);
    }

    // Halo fill (fp16). OOB -> zeros == unfold's zero padding of binarized mask.
    const int hRows = TH + nDy - 1;      // 9 (half0) / 8 (half1)
    const int hsz   = HW_ * hRows;
    __half* hR  = (__half*)sR;
    __half* hG  = (__half*)sGg;
    __half* hB  = (__half*)sBb;
    __half* hA  = (__half*)sA;
    __half* hBB = (__half*)sB;
    for (int i = tid; i < hsz; i += NT) {
        int ly = i / HW_;
        int lx = i - ly * HW_;
        int gy = ty0 + d0 - RAD + ly;
        int gx = tx0 + lx - RAD;
        float r = 0.f, g = 0.f, b = 0.f, A = 0.f, B = 0.f;
        if (gx >= 0 && gx < W && gy >= 0 && gy < H) {
            int idx = gy * W + gx;
            float ms = mp[idx];
            if (isnan(ms) || ms < 1.0f) ms = 0.0f;   // binarize, keep value if >=1
            float s = 1.0f / (1.0f + __expf(-yp[idx]));
            r = xr[idx] * RGB_SCALE;
            g = xg[idx] * RGB_SCALE;
            b = xb[idx] * RGB_SCALE;
            A = ms * s;
            B = ms - A;                              // ms*(1-s)
        }
        int o = ly * (2 * HC) + lx;
        hR[o]  = __float2half_rn(r);
        hG[o]  = __float2half_rn(g);
        hB[o]  = __float2half_rn(b);
        hA[o]  = __float2half_rn(A);
        hBB[o] = __float2half_rn(B);
    }
    __syncthreads();

    const int px0 = tx0 + 2 * cx;
    const int py  = ty0 + cy;

    // Centers from gmem, quantized through the SAME fp16 rounding as the halo.
    __half2 c0r, c0g, c0b, c1r, c1g, c1b;
    {
        int i0 = py * W + px0;
        c0r = __float2half2_rn(xr[i0] * RGB_SCALE);
        c0g = __float2half2_rn(xg[i0] * RGB_SCALE);
        c0b = __float2half2_rn(xb[i0] * RGB_SCALE);
        c1r = __float2half2_rn(xr[i0 + 1] * RGB_SCALE);
        c1g = __float2half2_rn(xg[i0 + 1] * RGB_SCALE);
        c1b = __float2half2_rn(xb[i0 + 1] * RGB_SCALE);
    }
    const __half2 NINTH2 = __float2half2_rn(1.0f / 9.0f);
    const __half2 ZERO2  = __float2half2_rn(0.0f);

    float SA0 = 0.f, SB0 = 0.f, SA1 = 0.f, SB1 = 0.f;

    #define TAPP(qr,qg,qb,qa,qbb,cr,cg,cb,Gp,RA,RB) do {                     \
        __half2 dr_ = __hsub2(qr, cr);                                       \
        __half2 dg_ = __hsub2(qg, cg);                                       \
        __half2 db_ = __hsub2(qb, cb);                                       \
        __half2 t_  = __hmul2(dr_, __hneg2(dr_));                            \
        t_ = __hfma2(dg_, __hneg2(dg_), t_);                                 \
        t_ = __hfma2(db_, __hneg2(db_), t_);                                 \
        __half2 e_ = h2exp2(t_);                                             \
        __half2 w_ = __hmul2(__hadd2(e_, NINTH2), Gp);                       \
        RA = __hfma2(w_, qa, RA);                                            \
        RB = __hfma2(w_, qbb, RB);                                           \
    } while (0)

    for (int dyi = 0; dyi < nDy; dyi++) {
        const int row  = cy + dyi;         // halo-local row
        const int grow = d0 + dyi;         // gaussian-table row
        const __half2* __restrict__ pr  = &sR [row][cx];
        const __half2* __restrict__ pg  = &sGg[row][cx];
        const __half2* __restrict__ pb  = &sBb[row][cx];
        const __half2* __restrict__ pa  = &sA [row][cx];
        const __half2* __restrict__ pbb = &sB [row][cx];
        const __half2* __restrict__ g0  = sGp0[grow];
        const __half2* __restrict__ g1  = sGp1[grow];

        __half2 ra0 = ZERO2, rb0 = ZERO2, ra1 = ZERO2, rb1 = ZERO2;
        #pragma unroll
        for (int k = 0; k < 6; k++) {
            __half2 qr  = pr[k];
            __half2 qg  = pg[k];
            __half2 qb  = pb[k];
            __half2 qa  = pa[k];
            __half2 qbb = pbb[k];
            TAPP(qr, qg, qb, qa, qbb, c0r, c0g, c0b, g0[k], ra0, rb0);
            TAPP(qr, qg, qb, qa, qbb, c1r, c1g, c1b, g1[k], ra1, rb1);
        }
        // Row-partial fp16 -> fp32 spill (bounds fp16 accumulation error)
        float2 f;
        f = __half22float2(ra0); SA0 += f.x + f.y;
        f = __half22float2(rb0); SB0 += f.x + f.y;
        f = __half22float2(ra1); SA1 += f.x + f.y;
        f = __half22float2(rb1); SB1 += f.x + f.y;
    }

    // Center combine (partial over this dy-half; linear in SA/SB)
    float num = 0.f, den = 0.f;
    if (py < H && px0 < W) {
        {
            int idx = py * W + px0;
            float md = dp[idx];
            if (isnan(md) || md < 1.0f) md = 0.0f;
            float sp = 1.0f / (1.0f + __expf(-yp[idx]));
            num += md * fmaf(sp, SB0, (1.0f - sp) * SA0);
            if (half == 0) den += md;              // denominator counted once
        }
        if (px0 + 1 < W) {
            int idx = py * W + px0 + 1;
            float md = dp[idx];
            if (isnan(md) || md < 1.0f) md = 0.0f;
            float sp = 1.0f / (1.0f + __expf(-yp[idx]));
            num += md * fmaf(sp, SB1, (1.0f - sp) * SA1);
            if (half == 0) den += md;
        }
    }

    // Block reduction
    #pragma unroll
    for (int off = 16; off > 0; off >>= 1) {
        num += __shfl_down_sync(0xffffffffu, num, off);
        den += __shfl_down_sync(0xffffffffu, den, off);
    }
    int wid = tid >> 5, lid = tid & 31;
    if (lid == 0) { red[wid] = num; red[4 + wid] = den; }
    __syncthreads();

    if (tid == 0) {
        float ns = red[0] + red[1] + red[2] + red[3];
        float ds = red[4] + red[5] + red[6] + red[7];
        atomicAdd(&g_num, (double)ns);
        atomicAdd(&g_den, (double)ds);
        __threadfence();
        unsigned old = atomicAdd(&g_ticket, 1u);
        if (old == nblocks - 1u) {           // last block finalizes + resets
            double nn = g_num;
            double dd = g_den;
            if (dd < 1.0) dd = 1.0;
            out[0] = (float)(nn / dd);
            g_num = 0.0;
            g_den = 0.0;
            g_ticket = 0u;
        }
    }
}

extern "C" void kernel_launch(void* const* d_in, const int* in_sizes, int n_in,
                              void* d_out, int out_size) {
    const float* x    = (const float*)d_in[0];
    const float* y    = (const float*)d_in[1];
    const float* msrc = (const float*)d_in[2];
    const float* mdst = (const float*)d_in[3];
    float* out = (float*)d_out;

    const int H = 256, W = 256;
    const int N = in_sizes[1] / (H * W);

    dim3 block(BX, BY, 1);
    dim3 grid((W + TW - 1) / TW, (H + TH - 1) / TH, 2 * N);  // dy-split halves
    unsigned nblocks = grid.x * grid.y * grid.z;
    crf_loss_kernel<<<grid, block>>>(x, y, msrc, mdst, out, H, W, nblocks);
}